// round 14
// baseline (speedup 1.0000x reference)
#include <cuda_runtime.h>
#include <cuda_bf16.h>
#include <cstdint>

typedef unsigned int u32; typedef unsigned short u16;

// AttentionMV B=T=1024, E=128. mma.sync bf16 3-pass split. R13.
// Batch split across 2 CTAs by f-half -> small CTA (94KB smem, ~110 regs)
// -> 2 independent CTAs/SM (different batches) -> phase-drifted MMA streams.
//  CTA (bb, fhalf): GEMM1 u[t][f-half] over all t (TT=32 tiles);
//  GEMM2 pre[e][f-half] += vT x u (full t contraction), pre -> gmem scratch.
//  Kernel2: softmax over full f + output.

constexpr int NT = 256;
constexpr u32 WFH=0, WFL=16384;        // W frags (64f x 128e) hi/lo
constexpr u32 MFH=32768, MFL=40960;    // m frags (32t x 128e) hi/lo
constexpr u32 UFH=49152, UFL=53248;    // u frags (32t x 64f) hi/lo
constexpr u32 VT0=57344, VT1=73728;    // vT frag slots (128e x 32t, hi+lo 16K)
constexpr u32 SP_OFF=90112;            // 8*128 f32 colsum partials
constexpr u32 SMEM_BYTES=94208;

__device__ u16 g_vtFH[131072];         // vT A-frag images (TT=64 indexing)
__device__ u16 g_vtFL[131072];
__device__ float g_pre[16777216];      // pre scratch [1024][128][128]
__device__ float g_s[131072];          // colsums [1024][128]

__device__ __forceinline__ float fast_tanh(float x){
    float e = __expf(2.0f*x);
    return 1.0f - __fdividef(2.0f, e+1.0f);
}
__device__ __forceinline__ float trunc_hi(float x){
    return __uint_as_float(__float_as_uint(x) & 0xffff0000u);
}
__device__ __forceinline__ u32 cvt_bf16x2(float hiArg, float loArg){
    u32 d; asm("cvt.rn.bf16x2.f32 %0, %1, %2;" : "=r"(d) : "f"(hiArg), "f"(loArg));
    return d;
}
__device__ __forceinline__ void mma16816(float* d, u32 a0,u32 a1,u32 a2,u32 a3,
                                         u32 b0,u32 b1){
    asm volatile("mma.sync.aligned.m16n8k16.row.col.f32.bf16.bf16.f32 "
        "{%0,%1,%2,%3}, {%4,%5,%6,%7}, {%8,%9}, {%0,%1,%2,%3};"
        : "+f"(d[0]),"+f"(d[1]),"+f"(d[2]),"+f"(d[3])
        : "r"(a0),"r"(a1),"r"(a2),"r"(a3),"r"(b0),"r"(b1));
}
__device__ __forceinline__ u32 smem_u32(const void* p){
    u32 a; asm("{ .reg .u64 t; cvta.to.shared.u64 t, %1; cvt.u32.u64 %0, t; }"
               : "=r"(a) : "l"(p));
    return a;
}
__device__ __forceinline__ void cp16(u32 dst, const void* src){
    asm volatile("cp.async.ca.shared.global [%0], [%1], 16;" :: "r"(dst), "l"(src));
}

// vT A-frag prep (verified R9 layout, 64-t tile indexing)
__global__ void vt_prep(const float* __restrict__ gv){
    int t = blockIdx.x, e = threadIdx.x;
    float x = gv[t*128 + e];
    u16 hi = (u16)(__float_as_uint(x) >> 16);
    u16 lo = __bfloat16_as_ushort(__float2bfloat16(x - trunc_hi(x)));
    int tile = t>>6, s = (t>>4)&3, tr = t&15;
    int kh = tr>>3, rs = (tr&7)>>1, byt = tr&1;
    int i = e>>4, eq = e&15, rh = eq>>3, q = eq&7;
    int reg = rh + 2*kh, lane = q*4 + rs;
    int idx = ((tile*32 + i*4 + s)*32 + lane)*8 + reg*2 + byt;
    g_vtFH[idx] = hi; g_vtFL[idx] = lo;
}

__global__ __launch_bounds__(NT,2)
void attn_mma(const float* __restrict__ gm, const float* __restrict__ gW,
              const float* __restrict__ gb)
{
    extern __shared__ char sm[];
    const u32 sbase = smem_u32(sm);
    const int tid=threadIdx.x, lane=tid&31, w=tid>>5;
    const int bb = blockIdx.x>>1, fhalf = blockIdx.x&1;
    const int eh = w>>2, fq = w&3;
    const int q=lane>>2, r2=(lane&3)*2;
    const float* Wb = gW + (size_t)bb*16384;
    const float4* mb4 = (const float4*)(gm + (size_t)bb*131072);

    const int m_ks = lane>>2, m_r = (lane>>1)&1;
    const int m_l  = w*4 + (lane&1)*2;

    // ---- W(f-half) -> A-frag layout
    for (int it=0; it<32; it++){
        int idx = it*NT + tid;
        int e = idx>>6, fl = idx&63;
        float x = __ldg(Wb + e*128 + fhalf*64 + fl);
        u16 hi = (u16)(__float_as_uint(x) >> 16);
        u16 lo = __bfloat16_as_ushort(__float2bfloat16(x - trunc_hi(x)));
        int w2=fl>>4, fr=fl&15, rh=fr>>3, qq=fr&7;
        int ks=e>>4, er=e&15, kh=er>>3, rs=(er&7)>>1, byt=er&1;
        u32 off = (u32)(((w2*8+ks)*32 + qq*4 + rs)*16 + (rh + 2*kh)*4 + byt*2);
        *(u16*)(sm + WFH + off) = hi;
        *(u16*)(sm + WFL + off) = lo;
    }

    float s4[4]={0,0,0,0};
    float4 mreg[4];

    auto cpvt = [&](int t32){
        u32 dst = (t32&1) ? VT1 : VT0;
        int t64 = t32>>1;
        int i = tid>>5, c = tid&31;
        size_t src = ((size_t)(t64*32 + i*4 + (t32&1)*2))*512 + c*32;
        u32 d = sbase + dst + (u32)(i*1024 + c*32);
        cp16(d,      (const char*)g_vtFH + src);
        cp16(d+16,   (const char*)g_vtFH + src + 16);
        cp16(d+8192, (const char*)g_vtFL + src);
        cp16(d+8192+16, (const char*)g_vtFL + src + 16);
    };
    auto msplit = [&](){
        #pragma unroll
        for (int j=0;j<4;j++){
            float4 x = mreg[j];
            s4[0]+=x.x; s4[1]+=x.y; s4[2]+=x.z; s4[3]+=x.w;
            u32 hA = __byte_perm(__float_as_uint(x.x), __float_as_uint(x.y), 0x7632);
            u32 hB = __byte_perm(__float_as_uint(x.z), __float_as_uint(x.w), 0x7632);
            float l0 = x.x - trunc_hi(x.x), l1 = x.y - trunc_hi(x.y);
            float l2 = x.z - trunc_hi(x.z), l3 = x.w - trunc_hi(x.w);
            u32 lA = cvt_bf16x2(l1, l0), lB = cvt_bf16x2(l3, l2);
            u32 blkH = MFH + (u32)(j*8 + m_ks)*256;
            u32 blkL = MFL + (u32)(j*8 + m_ks)*256;
            u32 iA = (u32)((m_l*2     + m_r + m_ks*8) & 63)*4;
            u32 iB = (u32)(((m_l+1)*2 + m_r + m_ks*8) & 63)*4;
            *(u32*)(sm + blkH + iA) = hA;
            *(u32*)(sm + blkH + iB) = hB;
            *(u32*)(sm + blkL + iA) = lA;
            *(u32*)(sm + blkL + iB) = lB;
        }
    };

    // ---- prologue
    #pragma unroll
    for (int j=0;j<4;j++) mreg[j] = __ldg(mb4 + j*NT + tid);
    cpvt(0);
    asm volatile("cp.async.commit_group;");

    float pre[4][2][4];
    #pragma unroll
    for (int i=0;i<4;i++)
        #pragma unroll
        for (int fb=0;fb<2;fb++)
            #pragma unroll
            for (int j=0;j<4;j++) pre[i][fb][j]=0.f;

    for (int t32=0; t32<32; t32++){
        __syncthreads();                        // bA: MF/UF/VT(cur slot) free
        if (t32<31) cpvt(t32+1);
        asm volatile("cp.async.commit_group;");
        msplit();
        if (t32<31){
            #pragma unroll
            for (int j=0;j<4;j++)
                mreg[j] = __ldg(mb4 + (t32+1)*1024 + j*NT + tid);
        }
        asm volatile("cp.async.wait_group 1;"); // vT(t32) landed
        __syncthreads();                        // bB: MF + VT visible

        // bias prefetch (8 values)
        float bv[8];
        #pragma unroll
        for (int nb=0;nb<2;nb++)
            #pragma unroll
            for (int c=0;c<4;c++){
                int tg = t32*32 + eh*16 + nb*8 + r2 + (c&1);
                int fg = fhalf*64 + fq*16 + q + 8*(c>>1);
                bv[nb*4+c] = __ldg(gb + (size_t)tg*128 + fg);
            }

        // ---- GEMM1: f rows fq*16..+15, t cols eh*16..+15 (even/odd ks accums)
        float d1[2][2][4];
        #pragma unroll
        for (int p=0;p<2;p++)
            #pragma unroll
            for (int nb=0;nb<2;nb++)
                #pragma unroll
                for (int c=0;c<4;c++) d1[p][nb][c]=0.f;
        #pragma unroll
        for (int ks=0;ks<8;ks++){
            uint4 ahv = *(const uint4*)(sm + WFH + (u32)(((fq*8+ks)*32+lane)*16));
            uint4 alv = *(const uint4*)(sm + WFL + (u32)(((fq*8+ks)*32+lane)*16));
            u32 bpos = (u32)(((lane*2) + ks*8) & 63)*4;
            uint2 bh[2], bl[2];
            #pragma unroll
            for (int nb=0;nb<2;nb++){
                bh[nb] = *(const uint2*)(sm + MFH + (u32)(((eh*2+nb)*8+ks)*256) + bpos);
                bl[nb] = *(const uint2*)(sm + MFL + (u32)(((eh*2+nb)*8+ks)*256) + bpos);
            }
            float* a0 = d1[ks&1][0];
            float* a1 = d1[ks&1][1];
            mma16816(a0, ahv.x,ahv.y,ahv.z,ahv.w, bh[0].x,bh[0].y);
            mma16816(a1, ahv.x,ahv.y,ahv.z,ahv.w, bh[1].x,bh[1].y);
            mma16816(a0, ahv.x,ahv.y,ahv.z,ahv.w, bl[0].x,bl[0].y);
            mma16816(a1, ahv.x,ahv.y,ahv.z,ahv.w, bl[1].x,bl[1].y);
            mma16816(a0, alv.x,alv.y,alv.z,alv.w, bh[0].x,bh[0].y);
            mma16816(a1, alv.x,alv.y,alv.z,alv.w, bh[1].x,bh[1].y);
        }

        // ---- tanh + split + UF store
        #pragma unroll
        for (int nb=0;nb<2;nb++){
            float uv[4];
            #pragma unroll
            for (int c=0;c<4;c++)
                uv[c] = fast_tanh(d1[0][nb][c] + d1[1][nb][c] + bv[nb*4+c]);
            #pragma unroll
            for (int fbi=0;fbi<2;fbi++){
                u32 h = __byte_perm(__float_as_uint(uv[fbi*2]),
                                    __float_as_uint(uv[fbi*2+1]), 0x7632);
                u32 l = cvt_bf16x2(uv[fbi*2+1]-trunc_hi(uv[fbi*2+1]),
                                   uv[fbi*2]-trunc_hi(uv[fbi*2]));
                u32 off = (u32)((eh*8 + fq*2+fbi)*256) + lane*8 + nb*4;
                *(u32*)(sm + UFH + off) = h;
                *(u32*)(sm + UFL + off) = l;
            }
        }
        __syncthreads();                        // bC: UF complete

        // ---- GEMM2: pre[e = eh*64..+63][f = fq*16..+15], k-steps s=0,1
        const u32 VTp = (t32&1) ? VT1 : VT0;
        #pragma unroll
        for (int s=0;s<2;s++){
            uint4 aH[4], aL[4];
            #pragma unroll
            for (int ii=0;ii<4;ii++){
                u32 off = (u32)(((eh*4+ii)*2+s)*512) + lane*16;
                aH[ii] = *(const uint4*)(sm + VTp + off);
                aL[ii] = *(const uint4*)(sm + VTp + 8192 + off);
            }
            uint2 bH[2], bL[2];
            #pragma unroll
            for (int fbi=0;fbi<2;fbi++){
                u32 off = (u32)((s*8 + fq*2+fbi)*256) + lane*8;
                bH[fbi] = *(const uint2*)(sm + UFH + off);
                bL[fbi] = *(const uint2*)(sm + UFL + off);
            }
            #pragma unroll
            for (int ii=0;ii<4;ii++)
                #pragma unroll
                for (int fbi=0;fbi<2;fbi++)
                    mma16816(pre[ii][fbi], aH[ii].x,aH[ii].y,aH[ii].z,aH[ii].w,
                             bH[fbi].x, bH[fbi].y);
            #pragma unroll
            for (int ii=0;ii<4;ii++)
                #pragma unroll
                for (int fbi=0;fbi<2;fbi++)
                    mma16816(pre[ii][fbi], aH[ii].x,aH[ii].y,aH[ii].z,aH[ii].w,
                             bL[fbi].x, bL[fbi].y);
            #pragma unroll
            for (int ii=0;ii<4;ii++)
                #pragma unroll
                for (int fbi=0;fbi<2;fbi++)
                    mma16816(pre[ii][fbi], aL[ii].x,aL[ii].y,aL[ii].z,aL[ii].w,
                             bH[fbi].x, bH[fbi].y);
        }
    }

    // ---- write pre slice to gmem
    float* pb = g_pre + (size_t)bb*16384;
    #pragma unroll
    for (int ii=0;ii<4;ii++)
        #pragma unroll
        for (int fbi=0;fbi<2;fbi++){
            int e0 = eh*64 + ii*16 + q;
            int fg = fhalf*64 + fq*16 + fbi*8 + r2;
            *(float2*)(pb + e0*128 + fg)     = make_float2(pre[ii][fbi][0], pre[ii][fbi][1]);
            *(float2*)(pb + (e0+8)*128 + fg) = make_float2(pre[ii][fbi][2], pre[ii][fbi][3]);
        }

    // ---- colsum (fhalf==0 CTA writes)
    float* SP=(float*)(sm+SP_OFF);
    *(float4*)(SP + w*128 + lane*4) = make_float4(s4[0],s4[1],s4[2],s4[3]);
    __syncthreads();
    if (fhalf==0 && tid<128){
        float ss=0;
        #pragma unroll
        for (int ww=0;ww<8;ww++) ss+=SP[ww*128+tid];
        g_s[bb*128+tid] = ss;
    }
}

// ---- kernel2: softmax over f + out[f] = sum_e coef_e * ex[e][f]
constexpr u32 K2_SMEM = 128*132*4 + 512;
__global__ void softmax_out(float* __restrict__ gout){
    extern __shared__ float sm2[];
    float* EX = sm2;                 // [f*132 + e]
    float* CF = sm2 + 128*132;
    const int tid = threadIdx.x, bb = blockIdx.x;
    const float4* pr = (const float4*)(g_pre + (size_t)bb*16384 + tid*128);
    float mx = -1e30f;
    float4 row[32];
    #pragma unroll 8
    for (int j=0;j<32;j++){
        row[j] = __ldg(pr + j);
        mx = fmaxf(mx, fmaxf(fmaxf(row[j].x,row[j].y), fmaxf(row[j].z,row[j].w)));
    }
    float sum = 0.f;
    #pragma unroll 4
    for (int j=0;j<32;j++){
        float e0=__expf(row[j].x-mx), e1=__expf(row[j].y-mx);
        float e2=__expf(row[j].z-mx), e3=__expf(row[j].w-mx);
        sum += (e0+e1)+(e2+e3);
        EX[(j*4+0)*132+tid]=e0; EX[(j*4+1)*132+tid]=e1;
        EX[(j*4+2)*132+tid]=e2; EX[(j*4+3)*132+tid]=e3;
    }
    CF[tid] = g_s[bb*128+tid] * __fdividef(1.f, sum);
    __syncthreads();
    float acc=0;
    #pragma unroll 8
    for (int e=0;e<128;e++) acc = fmaf(CF[e], EX[tid*132+e], acc);
    gout[(size_t)bb*128+tid] = acc;
}

extern "C" void kernel_launch(void* const* d_in, const int* in_sizes, int n_in,
                              void* d_out, int out_size) {
    const float* m = (const float*)d_in[0];
    const float* v = (const float*)d_in[1];
    const float* W = (const float*)d_in[2];
    const float* b = (const float*)d_in[3];
    float* out = (float*)d_out;

    vt_prep<<<1024, 128>>>(v);
    cudaFuncSetAttribute(attn_mma, cudaFuncAttributeMaxDynamicSharedMemorySize,
                         (int)SMEM_BYTES);
    attn_mma<<<2048, NT, SMEM_BYTES>>>(m, W, b);
    cudaFuncSetAttribute(softmax_out, cudaFuncAttributeMaxDynamicSharedMemorySize,
                         (int)K2_SMEM);
    softmax_out<<<1024, 128, K2_SMEM>>>(out);
}